// round 9
// baseline (speedup 1.0000x reference)
#include <cuda_runtime.h>
#include <cuda_fp16.h>
#include <cstdint>

#define E_DIM 256
#define D_DIM 128
#define MT    64           // tokens per CTA
#define NCH   8            // chunks (k32 each)
#define STG_BY 28672u      // stage bytes: x 2*2048B + W 3*8192B
#define NSTG  3

// attention-phase smem (floats); GEMM stages (3*28672B = 84KB) alias low region
#define QSTR    132
#define F_Q     0
#define F_K     8448
#define F_V     16896
#define F_PR    25344
#define F_BI    25856
#define SMEM_FLOATS 26240          // 104,960 B -> 2 CTAs/SM

__device__ __half g_xh[16777216];      // x, fragment-major per 64-token tile (32MB)
__device__ __half g_Wh[3 * 65536];     // W, fragment-major
__device__ float  g_b[3 * E_DIM];

#define MMA_F16(c, a, b0, b1) \
    asm volatile("mma.sync.aligned.m16n8k16.row.col.f32.f16.f16.f32 " \
        "{%0,%1,%2,%3}, {%4,%5,%6,%7}, {%8,%9}, {%0,%1,%2,%3};" \
        : "+f"((c)[0]), "+f"((c)[1]), "+f"((c)[2]), "+f"((c)[3]) \
        : "r"((a)[0]), "r"((a)[1]), "r"((a)[2]), "r"((a)[3]), "r"(b0), "r"(b1))

#define CP_ASYNC16(dst, src) \
    asm volatile("cp.async.ca.shared.global [%0], [%1], 16;" :: "r"(dst), "l"(src))
#define CP_COMMIT()  asm volatile("cp.async.commit_group;" ::: "memory")
#define CP_WAIT1()   asm volatile("cp.async.wait_group 1;" ::: "memory")
#define CP_WAIT0()   asm volatile("cp.async.wait_group 0;" ::: "memory")

// ---- x -> fp16 fragment-major tiles ----
// per 64-token tile: [k16(16)][mtile(4)][lane(32)][8 halfs]
__global__ void prex_kernel(const float* __restrict__ x) {
    __shared__ uint32_t sh[8192];          // 32KB
    const int tid = threadIdx.x;
    const float4* xg4 = (const float4*)(x + (size_t)blockIdx.x * MT * E_DIM);
#pragma unroll
    for (int i = 0; i < 16; ++i) {
        int idx = i * 256 + tid;           // 4096 float4
        int m = idx >> 6, k = (idx & 63) << 2;
        float4 v = xg4[idx];
        int row = m & 15, mtile = m >> 4, k16 = k >> 4;
#pragma unroll
        for (int j = 0; j < 2; ++j) {
            int kk = k + 2 * j;
            int lane = ((row & 7) << 2) | ((kk & 7) >> 1);
            int reg  = ((row >> 3) & 1) | (((kk >> 3) & 1) << 1);
            __half2 hv = j ? __floats2half2_rn(v.z, v.w) : __floats2half2_rn(v.x, v.y);
            sh[((k16 * 4 + mtile) * 32 + lane) * 4 + reg] = *(uint32_t*)&hv;
        }
    }
    __syncthreads();
    uint4* go = (uint4*)(g_xh + (size_t)blockIdx.x * 16384);
    const uint4* si = (const uint4*)sh;
#pragma unroll
    for (int i = 0; i < 8; ++i) go[i * 256 + tid] = si[i * 256 + tid];
}

// ---- W (P folded into Wq/Wk) -> fp16 fragment-major ----
// idx = (p*2+h)*32768 + k16*2048 + wn*512 + pair*256 + lane*8 + sub*4 + reg*2 + halfidx
// 8 independent accumulator chains for ILP.
__global__ void prep_kernel(const float* __restrict__ Wq, const float* __restrict__ bq,
                            const float* __restrict__ Wk, const float* __restrict__ bk,
                            const float* __restrict__ Wv, const float* __restrict__ bv,
                            const float* __restrict__ P) {
    int e = blockIdx.x, j = threadIdx.x;        // e = k, j = output col
    int h = j >> 7, jm = j & 127;
    const float* wqp = Wq + (size_t)h * D_DIM * E_DIM + e;
    const float* wkp = Wk + (size_t)h * D_DIM * E_DIM + e;
    float aq0 = 0.f, aq1 = 0.f, aq2 = 0.f, aq3 = 0.f;
    float ak0 = 0.f, ak1 = 0.f, ak2 = 0.f, ak3 = 0.f;
#pragma unroll
    for (int d = 0; d < D_DIM; d += 4) {
        float p0 = P[(d + 0) * D_DIM + jm];
        float p1 = P[(d + 1) * D_DIM + jm];
        float p2 = P[(d + 2) * D_DIM + jm];
        float p3 = P[(d + 3) * D_DIM + jm];
        aq0 = fmaf(wqp[(size_t)(d + 0) * E_DIM], p0, aq0);
        aq1 = fmaf(wqp[(size_t)(d + 1) * E_DIM], p1, aq1);
        aq2 = fmaf(wqp[(size_t)(d + 2) * E_DIM], p2, aq2);
        aq3 = fmaf(wqp[(size_t)(d + 3) * E_DIM], p3, aq3);
        ak0 = fmaf(wkp[(size_t)(d + 0) * E_DIM], p0, ak0);
        ak1 = fmaf(wkp[(size_t)(d + 1) * E_DIM], p1, ak1);
        ak2 = fmaf(wkp[(size_t)(d + 2) * E_DIM], p2, ak2);
        ak3 = fmaf(wkp[(size_t)(d + 3) * E_DIM], p3, ak3);
    }
    float aq = (aq0 + aq1) + (aq2 + aq3);
    float ak = (ak0 + ak1) + (ak2 + ak3);

    int k16 = e >> 4, reg = (e >> 3) & 1, halfidx = e & 1;
    int lane = ((jm & 7) << 2) | ((e & 7) >> 1);
    int wn = jm >> 5, nt = (jm >> 3) & 3, pair = nt >> 1, sub = nt & 1;
    size_t inner = (size_t)k16 * 2048 + wn * 512 + pair * 256 + lane * 8 + sub * 4 + reg * 2 + halfidx;
    g_Wh[(size_t)(0 * 2 + h) * 32768 + inner] = __float2half(aq);
    g_Wh[(size_t)(1 * 2 + h) * 32768 + inner] = __float2half(ak);
    g_Wh[(size_t)(2 * 2 + h) * 32768 + inner] = __float2half(Wv[j * E_DIM + e]);
    if (e == 0) {
        float bqe = 0.f, bke = 0.f;
        for (int d = 0; d < D_DIM; ++d) {
            float p = P[d * D_DIM + jm];
            bqe = fmaf(bq[h * D_DIM + d], p, bqe);
            bke = fmaf(bk[h * D_DIM + d], p, bke);
        }
        g_b[0 * E_DIM + j] = bqe;
        g_b[1 * E_DIM + j] = bke;
        g_b[2 * E_DIM + j] = bv[j];
    }
}

// CTA = 64 tokens x 1 head; merged qkv fp16 k-loop (k32 chunks, 2 k16 sub-steps),
// 3-stage cp.async ring, one barrier per chunk. Then in-CTA block attention.
// stage layout (f4 units): x [0,256) = 2 k16 x 128 f4;
//                          W [256,1792) = 3p x 512 f4, each p = 2 k16 x 256 f4.
__global__ __launch_bounds__(256, 2)
void fused_kernel(float* __restrict__ out) {
    extern __shared__ float sm[];
    const int tid  = threadIdx.x;
    const int w    = tid >> 5, lane = tid & 31;
    const int wm   = w >> 2, wn = w & 3;          // warp grid 2x4 over [64,128]
    const int tile = blockIdx.x >> 1, head = blockIdx.x & 1;

    uint32_t smb;
    asm("{\n\t.reg .u64 t;\n\tcvta.to.shared.u64 t, %1;\n\tcvt.u32.u64 %0, t;\n\t}"
        : "=r"(smb) : "l"(sm));

    const __half* xsrc = g_xh + (size_t)tile * 16384;
    const __half* wsrc = g_Wh + (size_t)head * 32768;

    auto issue = [&](int c) {
        uint32_t bb = smb + (uint32_t)(c % NSTG) * STG_BY;
        // x: 2048 halfs = 256 f4, one per thread
        CP_ASYNC16(bb + (uint32_t)tid * 16u, xsrc + (size_t)c * 2048 + tid * 8);
        // W: 3p x 4096 halfs = 1536 f4, six per thread (identity copy)
#pragma unroll
        for (int i = 0; i < 6; ++i) {
            int t = i * 256 + tid;                 // 0..1535
            int p = t >> 9, r = t & 511;
            CP_ASYNC16(bb + 4096u + (uint32_t)t * 16u,
                       wsrc + (size_t)p * 65536 + c * 4096 + r * 8);
        }
        CP_COMMIT();
    };

    // stage bias
    for (int i = tid; i < 384; i += 256)
        sm[F_BI + i] = g_b[(i >> 7) * E_DIM + head * D_DIM + (i & 127)];

    issue(0); issue(1);
    __syncthreads();                               // bias visible

    float acc[3][2][4][4];
#pragma unroll
    for (int p = 0; p < 3; ++p)
#pragma unroll
        for (int mi = 0; mi < 2; ++mi)
#pragma unroll
            for (int ni = 0; ni < 4; ++ni) {
                int col = wn * 32 + ni * 8 + 2 * (lane & 3);
                float b0 = sm[F_BI + p * 128 + col], b1 = sm[F_BI + p * 128 + col + 1];
                acc[p][mi][ni][0] = b0; acc[p][mi][ni][1] = b1;
                acc[p][mi][ni][2] = b0; acc[p][mi][ni][3] = b1;
            }

    for (int c = 0; c < NCH; ++c) {
        if (c < NCH - 1) { CP_WAIT1(); } else { CP_WAIT0(); }
        __syncthreads();                           // chunk c visible to all
        const uint4* st = (const uint4*)((const char*)sm + (size_t)(c % NSTG) * STG_BY);
#pragma unroll
        for (int s = 0; s < 2; ++s) {              // two k16 sub-steps
            uint32_t a[2][4];
            *(uint4*)a[0] = st[s * 128 + (2 * wm + 0) * 32 + lane];
            *(uint4*)a[1] = st[s * 128 + (2 * wm + 1) * 32 + lane];
#pragma unroll
            for (int p = 0; p < 3; ++p) {
                // FIX (round 8 bug): per-p region is 512 f4 = two k16 of 256 f4,
                // so the k16 sub-step offset is s*256 (was wrongly s*128).
                uint4 bp0 = st[256 + p * 512 + s * 256 + wn * 64 + lane];
                uint4 bp1 = st[256 + p * 512 + s * 256 + wn * 64 + 32 + lane];
                MMA_F16(acc[p][0][0], a[0], bp0.x, bp0.y);
                MMA_F16(acc[p][1][0], a[1], bp0.x, bp0.y);
                MMA_F16(acc[p][0][1], a[0], bp0.z, bp0.w);
                MMA_F16(acc[p][1][1], a[1], bp0.z, bp0.w);
                MMA_F16(acc[p][0][2], a[0], bp1.x, bp1.y);
                MMA_F16(acc[p][1][2], a[1], bp1.x, bp1.y);
                MMA_F16(acc[p][0][3], a[0], bp1.z, bp1.w);
                MMA_F16(acc[p][1][3], a[1], bp1.z, bp1.w);
            }
        }
        if (c + 2 < NCH) issue(c + 2);             // buf (c-1)%3: all readers done
    }
    __syncthreads();

    // ---- stage q/k/v (GEMM stages now dead) ----
#pragma unroll
    for (int p = 0; p < 3; ++p) {
        float* stg = sm + p * 8448;
#pragma unroll
        for (int mi = 0; mi < 2; ++mi) {
            int row = wm * 32 + mi * 16 + (lane >> 2);
#pragma unroll
            for (int ni = 0; ni < 4; ++ni) {
                int col = wn * 32 + ni * 8 + 2 * (lane & 3);
                stg[row * QSTR + col]           = acc[p][mi][ni][0];
                stg[row * QSTR + col + 1]       = acc[p][mi][ni][1];
                stg[(row + 8) * QSTR + col]     = acc[p][mi][ni][2];
                stg[(row + 8) * QSTR + col + 1] = acc[p][mi][ni][3];
            }
        }
    }
    __syncthreads();

    // ---- block-diagonal attention: warp w -> block w ----
    float* qs = sm + F_Q; float* ks = sm + F_K; float* vs = sm + F_V;
    const float scl = 0.08838834764831845f;   // 1/sqrt(128)
    {
        int blk = w;
        int i0 = lane >> 3, j0 = lane & 7;
        const float4* q0 = (const float4*)(qs + (8 * blk + i0) * QSTR);
        const float4* q1 = (const float4*)(qs + (8 * blk + i0 + 4) * QSTR);
        const float4* k0 = (const float4*)(ks + (8 * blk + j0) * QSTR);
        float s0 = 0.f, s1 = 0.f;
#pragma unroll
        for (int t = 0; t < 32; ++t) {
            float4 kk = k0[t];
            float4 aa = q0[t];
            s0 += aa.x * kk.x + aa.y * kk.y + aa.z * kk.z + aa.w * kk.w;
            float4 cc = q1[t];
            s1 += cc.x * kk.x + cc.y * kk.y + cc.z * kk.z + cc.w * kk.w;
        }
        s0 *= scl; s1 *= scl;
        float m0 = s0, m1 = s1;
#pragma unroll
        for (int off = 1; off < 8; off <<= 1) {
            m0 = fmaxf(m0, __shfl_xor_sync(0xffffffffu, m0, off));
            m1 = fmaxf(m1, __shfl_xor_sync(0xffffffffu, m1, off));
        }
        float e0 = __expf(s0 - m0), e1 = __expf(s1 - m1);
        float d0 = e0, d1 = e1;
#pragma unroll
        for (int off = 1; off < 8; off <<= 1) {
            d0 += __shfl_xor_sync(0xffffffffu, d0, off);
            d1 += __shfl_xor_sync(0xffffffffu, d1, off);
        }
        sm[F_PR + blk * 64 + lane]      = e0 / d0;
        sm[F_PR + blk * 64 + 32 + lane] = e1 / d1;
        __syncwarp();

        const float* prob = sm + F_PR + blk * 64;
        float4 o[8];
#pragma unroll
        for (int i = 0; i < 8; ++i) o[i] = make_float4(0.f, 0.f, 0.f, 0.f);
#pragma unroll
        for (int j = 0; j < 8; ++j) {
            float4 v4 = *(const float4*)(vs + (8 * blk + j) * QSTR + lane * 4);
#pragma unroll
            for (int i = 0; i < 8; ++i) {
                float a = prob[i * 8 + j];
                o[i].x = fmaf(a, v4.x, o[i].x);
                o[i].y = fmaf(a, v4.y, o[i].y);
                o[i].z = fmaf(a, v4.z, o[i].z);
                o[i].w = fmaf(a, v4.w, o[i].w);
            }
        }
#pragma unroll
        for (int i = 0; i < 8; ++i) {
            size_t token = (size_t)tile * MT + 8 * blk + i;
            *(float4*)(out + token * E_DIM + head * D_DIM + lane * 4) = o[i];
        }
    }
}

extern "C" void kernel_launch(void* const* d_in, const int* in_sizes, int n_in,
                              void* d_out, int out_size) {
    const float* x  = (const float*)d_in[0];
    const float* Wq = (const float*)d_in[1];
    const float* bq = (const float*)d_in[2];
    const float* Wk = (const float*)d_in[3];
    const float* bk = (const float*)d_in[4];
    const float* Wv = (const float*)d_in[5];
    const float* bv = (const float*)d_in[6];
    const float* P  = (const float*)d_in[7];
    float* out = (float*)d_out;

    const int tokens = in_sizes[0] / E_DIM;      // B*N
    const int tiles  = tokens / MT;              // 1024
    const size_t smem = (size_t)SMEM_FLOATS * sizeof(float);   // 104,960 B

    cudaFuncSetAttribute(fused_kernel,
                         cudaFuncAttributeMaxDynamicSharedMemorySize, (int)smem);

    prep_kernel<<<E_DIM, E_DIM>>>(Wq, bq, Wk, bk, Wv, bv, P);
    prex_kernel<<<tiles, 256>>>(x);
    fused_kernel<<<tiles * 2, 256, smem>>>(out);
}

// round 10
// speedup vs baseline: 1.2315x; 1.2315x over previous
#include <cuda_runtime.h>
#include <cuda_fp16.h>
#include <cstdint>

#define E_DIM 256
#define D_DIM 128
#define MT    64           // tokens per CTA
#define NCH   16           // chunks (k16 each)
#define STG_BY 14336u      // stage bytes: x 2048B + W 3*4096B
#define NSTG  3

// attention-phase smem (floats); GEMM stages (3*14336B = 43KB) alias low region
#define QSTR    132
#define F_Q     0
#define F_K     8448
#define F_V     16896
#define F_PR    25344
#define F_BI    25856
#define SMEM_FLOATS 26240          // 104,960 B -> 2 CTAs/SM

// pre_kernel smem: P 16384 + wq 256 + wk 256 = 16896 floats (67,584 B)
#define PRE_SMEM_FLOATS 16896

__device__ __half g_xh[16777216];      // x, fragment-major per 64-token tile (32MB)
__device__ __half g_Wh[3 * 65536];     // W, fragment-major
__device__ float  g_b[3 * E_DIM];

#define MMA_F16(c, a, b0, b1) \
    asm volatile("mma.sync.aligned.m16n8k16.row.col.f32.f16.f16.f32 " \
        "{%0,%1,%2,%3}, {%4,%5,%6,%7}, {%8,%9}, {%0,%1,%2,%3};" \
        : "+f"((c)[0]), "+f"((c)[1]), "+f"((c)[2]), "+f"((c)[3]) \
        : "r"((a)[0]), "r"((a)[1]), "r"((a)[2]), "r"((a)[3]), "r"(b0), "r"(b1))

#define CP_ASYNC16(dst, src) \
    asm volatile("cp.async.ca.shared.global [%0], [%1], 16;" :: "r"(dst), "l"(src))
#define CP_COMMIT()  asm volatile("cp.async.commit_group;" ::: "memory")
#define CP_WAIT1()   asm volatile("cp.async.wait_group 1;" ::: "memory")
#define CP_WAIT0()   asm volatile("cp.async.wait_group 0;" ::: "memory")

// ---- merged setup kernel ----
// blocks [0,256):   prep — fold P into Wq/Wk, write W fp16 fragment-major
//                   (all operands staged in smem; dot runs on LDS, not L2)
// blocks [256,1280): prex — x -> fp16 fragment-major tiles
__global__ __launch_bounds__(256)
void pre_kernel(const float* __restrict__ x,
                const float* __restrict__ Wq, const float* __restrict__ bq,
                const float* __restrict__ Wk, const float* __restrict__ bk,
                const float* __restrict__ Wv, const float* __restrict__ bv,
                const float* __restrict__ P) {
    extern __shared__ float s[];
    const int tid = threadIdx.x;

    if (blockIdx.x < 256) {
        // ================= prep =================
        const int e = blockIdx.x;                 // input feature (k index)
        float* ps  = s;                           // P [128][128]
        float* wqs = s + 16384;                   // Wq column e (256: h*128+d)
        float* wks = s + 16640;                   // Wk column e

        wqs[tid] = Wq[(size_t)tid * E_DIM + e];
        wks[tid] = Wk[(size_t)tid * E_DIM + e];
#pragma unroll
        for (int i = 0; i < 16; ++i)
            ((float4*)ps)[i * 256 + tid] = ((const float4*)P)[i * 256 + tid];
        __syncthreads();

        const int j = tid, h = j >> 7, jm = j & 127;
        const float* whq = wqs + h * D_DIM;
        const float* whk = wks + h * D_DIM;
        float aq0 = 0.f, aq1 = 0.f, ak0 = 0.f, ak1 = 0.f;
#pragma unroll 8
        for (int d = 0; d < D_DIM; d += 2) {
            float p0 = ps[d * D_DIM + jm];
            float p1 = ps[(d + 1) * D_DIM + jm];
            aq0 = fmaf(whq[d],     p0, aq0);
            aq1 = fmaf(whq[d + 1], p1, aq1);
            ak0 = fmaf(whk[d],     p0, ak0);
            ak1 = fmaf(whk[d + 1], p1, ak1);
        }
        float aq = aq0 + aq1, ak = ak0 + ak1;

        // fragment-major store (validated round 7 layout)
        int k16 = e >> 4, reg = (e >> 3) & 1, halfidx = e & 1;
        int lane = ((jm & 7) << 2) | ((e & 7) >> 1);
        int wn = jm >> 5, nt = (jm >> 3) & 3, pair = nt >> 1, sub = nt & 1;
        size_t inner = (size_t)k16 * 2048 + wn * 512 + pair * 256
                     + lane * 8 + sub * 4 + reg * 2 + halfidx;
        g_Wh[(size_t)(0 * 2 + h) * 32768 + inner] = __float2half(aq);
        g_Wh[(size_t)(1 * 2 + h) * 32768 + inner] = __float2half(ak);
        g_Wh[(size_t)(2 * 2 + h) * 32768 + inner] = __float2half(Wv[(size_t)j * E_DIM + e]);

        if (e == 0) {
            float bqe = 0.f, bke = 0.f;
#pragma unroll 8
            for (int d = 0; d < D_DIM; ++d) {
                float p = ps[d * D_DIM + jm];
                bqe = fmaf(bq[h * D_DIM + d], p, bqe);
                bke = fmaf(bk[h * D_DIM + d], p, bke);
            }
            g_b[0 * E_DIM + j] = bqe;
            g_b[1 * E_DIM + j] = bke;
            g_b[2 * E_DIM + j] = bv[j];
        }
    } else {
        // ================= prex =================
        // per 64-token tile: [k16(16)][mtile(4)][lane(32)][8 halfs]
        const int tile = blockIdx.x - 256;
        uint32_t* sh = (uint32_t*)s;              // 32KB
        const float4* xg4 = (const float4*)(x + (size_t)tile * MT * E_DIM);
#pragma unroll
        for (int i = 0; i < 16; ++i) {
            int idx = i * 256 + tid;              // 4096 float4
            int m = idx >> 6, k = (idx & 63) << 2;
            float4 v = xg4[idx];
            int row = m & 15, mtile = m >> 4, k16 = k >> 4;
#pragma unroll
            for (int jj = 0; jj < 2; ++jj) {
                int kk = k + 2 * jj;
                int lane = ((row & 7) << 2) | ((kk & 7) >> 1);
                int reg  = ((row >> 3) & 1) | (((kk >> 3) & 1) << 1);
                __half2 hv = jj ? __floats2half2_rn(v.z, v.w) : __floats2half2_rn(v.x, v.y);
                sh[((k16 * 4 + mtile) * 32 + lane) * 4 + reg] = *(uint32_t*)&hv;
            }
        }
        __syncthreads();
        uint4* go = (uint4*)(g_xh + (size_t)tile * 16384);
        const uint4* si = (const uint4*)sh;
#pragma unroll
        for (int i = 0; i < 8; ++i) go[i * 256 + tid] = si[i * 256 + tid];
    }
}

// CTA = 64 tokens x 1 head; merged qkv fp16 k-loop (k16 chunks), 3-stage
// cp.async ring, one barrier per chunk. Then in-CTA block attention.
// (byte-identical to the round-7 mainloop, best measured)
__global__ __launch_bounds__(256, 2)
void fused_kernel(float* __restrict__ out) {
    extern __shared__ float sm[];
    const int tid  = threadIdx.x;
    const int w    = tid >> 5, lane = tid & 31;
    const int wm   = w >> 2, wn = w & 3;          // warp grid 2x4 over [64,128]
    const int tile = blockIdx.x >> 1, head = blockIdx.x & 1;

    uint32_t smb;
    asm("{\n\t.reg .u64 t;\n\tcvta.to.shared.u64 t, %1;\n\tcvt.u32.u64 %0, t;\n\t}"
        : "=r"(smb) : "l"(sm));

    const __half* xsrc = g_xh + (size_t)tile * 16384;
    const __half* wsrc = g_Wh + (size_t)head * 32768;

    auto issue = [&](int c) {
        uint32_t bb = smb + (uint32_t)(c % NSTG) * STG_BY;
        if (tid < 128)
            CP_ASYNC16(bb + (uint32_t)tid * 16u, xsrc + (size_t)c * 1024 + tid * 8);
#pragma unroll
        for (int i = 0; i < 3; ++i) {
            int t = i * 256 + tid;                 // 0..767
            int p = t >> 8, r = t & 255;
            CP_ASYNC16(bb + 2048u + (uint32_t)t * 16u,
                       wsrc + (size_t)p * 65536 + c * 2048 + r * 8);
        }
        CP_COMMIT();
    };

    // stage bias
    for (int i = tid; i < 384; i += 256)
        sm[F_BI + i] = g_b[(i >> 7) * E_DIM + head * D_DIM + (i & 127)];

    issue(0); issue(1);
    __syncthreads();                               // bias visible

    float acc[3][2][4][4];
#pragma unroll
    for (int p = 0; p < 3; ++p)
#pragma unroll
        for (int mi = 0; mi < 2; ++mi)
#pragma unroll
            for (int ni = 0; ni < 4; ++ni) {
                int col = wn * 32 + ni * 8 + 2 * (lane & 3);
                float b0 = sm[F_BI + p * 128 + col], b1 = sm[F_BI + p * 128 + col + 1];
                acc[p][mi][ni][0] = b0; acc[p][mi][ni][1] = b1;
                acc[p][mi][ni][2] = b0; acc[p][mi][ni][3] = b1;
            }

    for (int c = 0; c < NCH; ++c) {
        if (c < NCH - 1) { CP_WAIT1(); } else { CP_WAIT0(); }
        __syncthreads();                           // chunk c visible to all
        const uint4* st = (const uint4*)((const char*)sm + (size_t)(c % NSTG) * STG_BY);

        uint32_t a[2][4];
        *(uint4*)a[0] = st[(2 * wm + 0) * 32 + lane];
        *(uint4*)a[1] = st[(2 * wm + 1) * 32 + lane];
#pragma unroll
        for (int p = 0; p < 3; ++p) {
            uint4 bp0 = st[128 + p * 256 + wn * 64 + lane];
            uint4 bp1 = st[128 + p * 256 + wn * 64 + 32 + lane];
            MMA_F16(acc[p][0][0], a[0], bp0.x, bp0.y);
            MMA_F16(acc[p][1][0], a[1], bp0.x, bp0.y);
            MMA_F16(acc[p][0][1], a[0], bp0.z, bp0.w);
            MMA_F16(acc[p][1][1], a[1], bp0.z, bp0.w);
            MMA_F16(acc[p][0][2], a[0], bp1.x, bp1.y);
            MMA_F16(acc[p][1][2], a[1], bp1.x, bp1.y);
            MMA_F16(acc[p][0][3], a[0], bp1.z, bp1.w);
            MMA_F16(acc[p][1][3], a[1], bp1.z, bp1.w);
        }
        if (c + 2 < NCH) issue(c + 2);             // buf (c-1)%3: all readers done
    }
    __syncthreads();

    // ---- stage q/k/v (GEMM stages now dead) ----
#pragma unroll
    for (int p = 0; p < 3; ++p) {
        float* stg = sm + p * 8448;
#pragma unroll
        for (int mi = 0; mi < 2; ++mi) {
            int row = wm * 32 + mi * 16 + (lane >> 2);
#pragma unroll
            for (int ni = 0; ni < 4; ++ni) {
                int col = wn * 32 + ni * 8 + 2 * (lane & 3);
                stg[row * QSTR + col]           = acc[p][mi][ni][0];
                stg[row * QSTR + col + 1]       = acc[p][mi][ni][1];
                stg[(row + 8) * QSTR + col]     = acc[p][mi][ni][2];
                stg[(row + 8) * QSTR + col + 1] = acc[p][mi][ni][3];
            }
        }
    }
    __syncthreads();

    // ---- block-diagonal attention: warp w -> block w ----
    float* qs = sm + F_Q; float* ks = sm + F_K; float* vs = sm + F_V;
    const float scl = 0.08838834764831845f;   // 1/sqrt(128)
    {
        int blk = w;
        int i0 = lane >> 3, j0 = lane & 7;
        const float4* q0 = (const float4*)(qs + (8 * blk + i0) * QSTR);
        const float4* q1 = (const float4*)(qs + (8 * blk + i0 + 4) * QSTR);
        const float4* k0 = (const float4*)(ks + (8 * blk + j0) * QSTR);
        float s0 = 0.f, s1 = 0.f;
#pragma unroll
        for (int t = 0; t < 32; ++t) {
            float4 kk = k0[t];
            float4 aa = q0[t];
            s0 += aa.x * kk.x + aa.y * kk.y + aa.z * kk.z + aa.w * kk.w;
            float4 cc = q1[t];
            s1 += cc.x * kk.x + cc.y * kk.y + cc.z * kk.z + cc.w * kk.w;
        }
        s0 *= scl; s1 *= scl;
        float m0 = s0, m1 = s1;
#pragma unroll
        for (int off = 1; off < 8; off <<= 1) {
            m0 = fmaxf(m0, __shfl_xor_sync(0xffffffffu, m0, off));
            m1 = fmaxf(m1, __shfl_xor_sync(0xffffffffu, m1, off));
        }
        float e0 = __expf(s0 - m0), e1 = __expf(s1 - m1);
        float d0 = e0, d1 = e1;
#pragma unroll
        for (int off = 1; off < 8; off <<= 1) {
            d0 += __shfl_xor_sync(0xffffffffu, d0, off);
            d1 += __shfl_xor_sync(0xffffffffu, d1, off);
        }
        sm[F_PR + blk * 64 + lane]      = e0 / d0;
        sm[F_PR + blk * 64 + 32 + lane] = e1 / d1;
        __syncwarp();

        const float* prob = sm + F_PR + blk * 64;
        float4 o[8];
#pragma unroll
        for (int i = 0; i < 8; ++i) o[i] = make_float4(0.f, 0.f, 0.f, 0.f);
#pragma unroll
        for (int j = 0; j < 8; ++j) {
            float4 v4 = *(const float4*)(vs + (8 * blk + j) * QSTR + lane * 4);
#pragma unroll
            for (int i = 0; i < 8; ++i) {
                float a = prob[i * 8 + j];
                o[i].x = fmaf(a, v4.x, o[i].x);
                o[i].y = fmaf(a, v4.y, o[i].y);
                o[i].z = fmaf(a, v4.z, o[i].z);
                o[i].w = fmaf(a, v4.w, o[i].w);
            }
        }
#pragma unroll
        for (int i = 0; i < 8; ++i) {
            size_t token = (size_t)tile * MT + 8 * blk + i;
            *(float4*)(out + token * E_DIM + head * D_DIM + lane * 4) = o[i];
        }
    }
}

extern "C" void kernel_launch(void* const* d_in, const int* in_sizes, int n_in,
                              void* d_out, int out_size) {
    const float* x  = (const float*)d_in[0];
    const float* Wq = (const float*)d_in[1];
    const float* bq = (const float*)d_in[2];
    const float* Wk = (const float*)d_in[3];
    const float* bk = (const float*)d_in[4];
    const float* Wv = (const float*)d_in[5];
    const float* bv = (const float*)d_in[6];
    const float* P  = (const float*)d_in[7];
    float* out = (float*)d_out;

    const int tokens = in_sizes[0] / E_DIM;      // B*N
    const int tiles  = tokens / MT;              // 1024
    const size_t pre_smem = (size_t)PRE_SMEM_FLOATS * sizeof(float);   // 67,584 B
    const size_t smem     = (size_t)SMEM_FLOATS * sizeof(float);       // 104,960 B

    cudaFuncSetAttribute(pre_kernel,
                         cudaFuncAttributeMaxDynamicSharedMemorySize, (int)pre_smem);
    cudaFuncSetAttribute(fused_kernel,
                         cudaFuncAttributeMaxDynamicSharedMemorySize, (int)smem);

    pre_kernel<<<256 + tiles, 256, pre_smem>>>(x, Wq, bq, Wk, bk, Wv, bv, P);
    fused_kernel<<<tiles * 2, 256, smem>>>(out);
}

// round 11
// speedup vs baseline: 1.2881x; 1.0460x over previous
#include <cuda_runtime.h>
#include <cuda_fp16.h>
#include <cstdint>

#define E_DIM 256
#define D_DIM 128
#define MT    64           // tokens per CTA
#define NCH   16           // chunks (k16 each)
#define STG_BY 2048u       // stage bytes: x only (1024 halfs)
#define NSTG  3

// attention-phase smem (floats); GEMM x-stages (3*2048B = 6KB) alias low region
#define QSTR    132
#define F_Q     0
#define F_K     8448
#define F_V     16896
#define F_PR    25344
#define F_BI    25856
#define SMEM_FLOATS 26240          // 104,960 B -> 2 CTAs/SM

// pre_kernel smem: P 16384 + wq 256 + wk 256 = 16896 floats (67,584 B)
#define PRE_SMEM_FLOATS 16896

__device__ __half g_xh[16777216];      // x, fragment-major per 64-token tile (32MB)
__device__ __half g_Wh[3 * 65536];     // W, fragment-major
__device__ float  g_b[3 * E_DIM];

#define MMA_F16(c, a, b0, b1) \
    asm volatile("mma.sync.aligned.m16n8k16.row.col.f32.f16.f16.f32 " \
        "{%0,%1,%2,%3}, {%4,%5,%6,%7}, {%8,%9}, {%0,%1,%2,%3};" \
        : "+f"((c)[0]), "+f"((c)[1]), "+f"((c)[2]), "+f"((c)[3]) \
        : "r"((a)[0]), "r"((a)[1]), "r"((a)[2]), "r"((a)[3]), "r"(b0), "r"(b1))

#define CP_ASYNC16(dst, src) \
    asm volatile("cp.async.ca.shared.global [%0], [%1], 16;" :: "r"(dst), "l"(src))
#define CP_COMMIT()  asm volatile("cp.async.commit_group;" ::: "memory")
#define CP_WAIT1()   asm volatile("cp.async.wait_group 1;" ::: "memory")
#define CP_WAIT0()   asm volatile("cp.async.wait_group 0;" ::: "memory")

// ---- merged setup kernel (unchanged from round 10) ----
// blocks [0,256):   prep — fold P into Wq/Wk, write W fp16 fragment-major (LDS dot)
// blocks [256,1280): prex — x -> fp16 fragment-major tiles
__global__ __launch_bounds__(256)
void pre_kernel(const float* __restrict__ x,
                const float* __restrict__ Wq, const float* __restrict__ bq,
                const float* __restrict__ Wk, const float* __restrict__ bk,
                const float* __restrict__ Wv, const float* __restrict__ bv,
                const float* __restrict__ P) {
    extern __shared__ float s[];
    const int tid = threadIdx.x;

    if (blockIdx.x < 256) {
        const int e = blockIdx.x;
        float* ps  = s;
        float* wqs = s + 16384;
        float* wks = s + 16640;

        wqs[tid] = Wq[(size_t)tid * E_DIM + e];
        wks[tid] = Wk[(size_t)tid * E_DIM + e];
#pragma unroll
        for (int i = 0; i < 16; ++i)
            ((float4*)ps)[i * 256 + tid] = ((const float4*)P)[i * 256 + tid];
        __syncthreads();

        const int j = tid, h = j >> 7, jm = j & 127;
        const float* whq = wqs + h * D_DIM;
        const float* whk = wks + h * D_DIM;
        float aq0 = 0.f, aq1 = 0.f, ak0 = 0.f, ak1 = 0.f;
#pragma unroll 8
        for (int d = 0; d < D_DIM; d += 2) {
            float p0 = ps[d * D_DIM + jm];
            float p1 = ps[(d + 1) * D_DIM + jm];
            aq0 = fmaf(whq[d],     p0, aq0);
            aq1 = fmaf(whq[d + 1], p1, aq1);
            ak0 = fmaf(whk[d],     p0, ak0);
            ak1 = fmaf(whk[d + 1], p1, ak1);
        }
        float aq = aq0 + aq1, ak = ak0 + ak1;

        int k16 = e >> 4, reg = (e >> 3) & 1, halfidx = e & 1;
        int lane = ((jm & 7) << 2) | ((e & 7) >> 1);
        int wn = jm >> 5, nt = (jm >> 3) & 3, pair = nt >> 1, sub = nt & 1;
        size_t inner = (size_t)k16 * 2048 + wn * 512 + pair * 256
                     + lane * 8 + sub * 4 + reg * 2 + halfidx;
        g_Wh[(size_t)(0 * 2 + h) * 32768 + inner] = __float2half(aq);
        g_Wh[(size_t)(1 * 2 + h) * 32768 + inner] = __float2half(ak);
        g_Wh[(size_t)(2 * 2 + h) * 32768 + inner] = __float2half(Wv[(size_t)j * E_DIM + e]);

        if (e == 0) {
            float bqe = 0.f, bke = 0.f;
#pragma unroll 8
            for (int d = 0; d < D_DIM; ++d) {
                float p = ps[d * D_DIM + jm];
                bqe = fmaf(bq[h * D_DIM + d], p, bqe);
                bke = fmaf(bk[h * D_DIM + d], p, bke);
            }
            g_b[0 * E_DIM + j] = bqe;
            g_b[1 * E_DIM + j] = bke;
            g_b[2 * E_DIM + j] = bv[j];
        }
    } else {
        const int tile = blockIdx.x - 256;
        uint32_t* sh = (uint32_t*)s;
        const float4* xg4 = (const float4*)(x + (size_t)tile * MT * E_DIM);
#pragma unroll
        for (int i = 0; i < 16; ++i) {
            int idx = i * 256 + tid;
            int m = idx >> 6, k = (idx & 63) << 2;
            float4 v = xg4[idx];
            int row = m & 15, mtile = m >> 4, k16 = k >> 4;
#pragma unroll
            for (int jj = 0; jj < 2; ++jj) {
                int kk = k + 2 * jj;
                int lane = ((row & 7) << 2) | ((kk & 7) >> 1);
                int reg  = ((row >> 3) & 1) | (((kk >> 3) & 1) << 1);
                __half2 hv = jj ? __floats2half2_rn(v.z, v.w) : __floats2half2_rn(v.x, v.y);
                sh[((k16 * 4 + mtile) * 32 + lane) * 4 + reg] = *(uint32_t*)&hv;
            }
        }
        __syncthreads();
        uint4* go = (uint4*)(g_xh + (size_t)tile * 16384);
        const uint4* si = (const uint4*)sh;
#pragma unroll
        for (int i = 0; i < 8; ++i) go[i * 256 + tid] = si[i * 256 + tid];
    }
}

// CTA = 64 tokens x 1 head. x via cp.async ring; W (B fragments) read DIRECTLY
// from L2-resident g_Wh — no smem staging. Then in-CTA block attention.
__global__ __launch_bounds__(256, 2)
void fused_kernel(float* __restrict__ out) {
    extern __shared__ float sm[];
    const int tid  = threadIdx.x;
    const int w    = tid >> 5, lane = tid & 31;
    const int wm   = w >> 2, wn = w & 3;          // warp grid 2x4 over [64,128]
    const int tile = blockIdx.x >> 1, head = blockIdx.x & 1;

    uint32_t smb;
    asm("{\n\t.reg .u64 t;\n\tcvta.to.shared.u64 t, %1;\n\tcvt.u32.u64 %0, t;\n\t}"
        : "=r"(smb) : "l"(sm));

    const __half* xsrc = g_xh + (size_t)tile * 16384;
    // per-warp B fragment pointer (f4 units): [p(8192)][k16(256)][wn*64 + lane]
    const uint4* wp = (const uint4*)(g_Wh + (size_t)head * 32768)
                      + (uint32_t)(wn * 64 + lane);

    auto issue = [&](int c) {
        uint32_t bb = smb + (uint32_t)(c % NSTG) * STG_BY;
        if (tid < 128)
            CP_ASYNC16(bb + (uint32_t)tid * 16u, xsrc + (size_t)c * 1024 + tid * 8);
        CP_COMMIT();
    };

    // stage bias
    for (int i = tid; i < 384; i += 256)
        sm[F_BI + i] = g_b[(i >> 7) * E_DIM + head * D_DIM + (i & 127)];

    issue(0); issue(1);
    __syncthreads();                               // bias visible

    float acc[3][2][4][4];
#pragma unroll
    for (int p = 0; p < 3; ++p)
#pragma unroll
        for (int mi = 0; mi < 2; ++mi)
#pragma unroll
            for (int ni = 0; ni < 4; ++ni) {
                int col = wn * 32 + ni * 8 + 2 * (lane & 3);
                float b0 = sm[F_BI + p * 128 + col], b1 = sm[F_BI + p * 128 + col + 1];
                acc[p][mi][ni][0] = b0; acc[p][mi][ni][1] = b1;
                acc[p][mi][ni][2] = b0; acc[p][mi][ni][3] = b1;
            }

    for (int c = 0; c < NCH; ++c) {
        // B fragments straight from L2 (W is hot: 384KB reused by all CTAs)
        uint4 B0 = __ldg(wp);             uint4 B1 = __ldg(wp + 32);
        uint4 B2 = __ldg(wp + 8192);      uint4 B3 = __ldg(wp + 8192 + 32);
        uint4 B4 = __ldg(wp + 16384);     uint4 B5 = __ldg(wp + 16384 + 32);

        if (c < NCH - 1) { CP_WAIT1(); } else { CP_WAIT0(); }
        __syncthreads();                           // x chunk c visible
        const uint4* st = (const uint4*)((const char*)sm + (size_t)(c % NSTG) * STG_BY);

        uint32_t a[2][4];
        *(uint4*)a[0] = st[(2 * wm + 0) * 32 + lane];
        *(uint4*)a[1] = st[(2 * wm + 1) * 32 + lane];

        MMA_F16(acc[0][0][0], a[0], B0.x, B0.y);
        MMA_F16(acc[0][1][0], a[1], B0.x, B0.y);
        MMA_F16(acc[0][0][1], a[0], B0.z, B0.w);
        MMA_F16(acc[0][1][1], a[1], B0.z, B0.w);
        MMA_F16(acc[0][0][2], a[0], B1.x, B1.y);
        MMA_F16(acc[0][1][2], a[1], B1.x, B1.y);
        MMA_F16(acc[0][0][3], a[0], B1.z, B1.w);
        MMA_F16(acc[0][1][3], a[1], B1.z, B1.w);

        MMA_F16(acc[1][0][0], a[0], B2.x, B2.y);
        MMA_F16(acc[1][1][0], a[1], B2.x, B2.y);
        MMA_F16(acc[1][0][1], a[0], B2.z, B2.w);
        MMA_F16(acc[1][1][1], a[1], B2.z, B2.w);
        MMA_F16(acc[1][0][2], a[0], B3.x, B3.y);
        MMA_F16(acc[1][1][2], a[1], B3.x, B3.y);
        MMA_F16(acc[1][0][3], a[0], B3.z, B3.w);
        MMA_F16(acc[1][1][3], a[1], B3.z, B3.w);

        MMA_F16(acc[2][0][0], a[0], B4.x, B4.y);
        MMA_F16(acc[2][1][0], a[1], B4.x, B4.y);
        MMA_F16(acc[2][0][1], a[0], B4.z, B4.w);
        MMA_F16(acc[2][1][1], a[1], B4.z, B4.w);
        MMA_F16(acc[2][0][2], a[0], B5.x, B5.y);
        MMA_F16(acc[2][1][2], a[1], B5.x, B5.y);
        MMA_F16(acc[2][0][3], a[0], B5.z, B5.w);
        MMA_F16(acc[2][1][3], a[1], B5.z, B5.w);

        wp += 256;                                 // next k16
        if (c + 2 < NCH) issue(c + 2);             // x buf (c-1)%3 free
    }
    __syncthreads();

    // ---- stage q/k/v (GEMM stages now dead) ----
#pragma unroll
    for (int p = 0; p < 3; ++p) {
        float* stg = sm + p * 8448;
#pragma unroll
        for (int mi = 0; mi < 2; ++mi) {
            int row = wm * 32 + mi * 16 + (lane >> 2);
#pragma unroll
            for (int ni = 0; ni < 4; ++ni) {
                int col = wn * 32 + ni * 8 + 2 * (lane & 3);
                stg[row * QSTR + col]           = acc[p][mi][ni][0];
                stg[row * QSTR + col + 1]       = acc[p][mi][ni][1];
                stg[(row + 8) * QSTR + col]     = acc[p][mi][ni][2];
                stg[(row + 8) * QSTR + col + 1] = acc[p][mi][ni][3];
            }
        }
    }
    __syncthreads();

    // ---- block-diagonal attention: warp w -> block w ----
    float* qs = sm + F_Q; float* ks = sm + F_K; float* vs = sm + F_V;
    const float scl = 0.08838834764831845f;   // 1/sqrt(128)
    {
        int blk = w;
        int i0 = lane >> 3, j0 = lane & 7;
        const float4* q0 = (const float4*)(qs + (8 * blk + i0) * QSTR);
        const float4* q1 = (const float4*)(qs + (8 * blk + i0 + 4) * QSTR);
        const float4* k0 = (const float4*)(ks + (8 * blk + j0) * QSTR);
        float s0 = 0.f, s1 = 0.f;
#pragma unroll
        for (int t = 0; t < 32; ++t) {
            float4 kk = k0[t];
            float4 aa = q0[t];
            s0 += aa.x * kk.x + aa.y * kk.y + aa.z * kk.z + aa.w * kk.w;
            float4 cc = q1[t];
            s1 += cc.x * kk.x + cc.y * kk.y + cc.z * kk.z + cc.w * kk.w;
        }
        s0 *= scl; s1 *= scl;
        float m0 = s0, m1 = s1;
#pragma unroll
        for (int off = 1; off < 8; off <<= 1) {
            m0 = fmaxf(m0, __shfl_xor_sync(0xffffffffu, m0, off));
            m1 = fmaxf(m1, __shfl_xor_sync(0xffffffffu, m1, off));
        }
        float e0 = __expf(s0 - m0), e1 = __expf(s1 - m1);
        float d0 = e0, d1 = e1;
#pragma unroll
        for (int off = 1; off < 8; off <<= 1) {
            d0 += __shfl_xor_sync(0xffffffffu, d0, off);
            d1 += __shfl_xor_sync(0xffffffffu, d1, off);
        }
        sm[F_PR + blk * 64 + lane]      = e0 / d0;
        sm[F_PR + blk * 64 + 32 + lane] = e1 / d1;
        __syncwarp();

        const float* prob = sm + F_PR + blk * 64;
        float4 o[8];
#pragma unroll
        for (int i = 0; i < 8; ++i) o[i] = make_float4(0.f, 0.f, 0.f, 0.f);
#pragma unroll
        for (int j = 0; j < 8; ++j) {
            float4 v4 = *(const float4*)(vs + (8 * blk + j) * QSTR + lane * 4);
#pragma unroll
            for (int i = 0; i < 8; ++i) {
                float a = prob[i * 8 + j];
                o[i].x = fmaf(a, v4.x, o[i].x);
                o[i].y = fmaf(a, v4.y, o[i].y);
                o[i].z = fmaf(a, v4.z, o[i].z);
                o[i].w = fmaf(a, v4.w, o[i].w);
            }
        }
#pragma unroll
        for (int i = 0; i < 8; ++i) {
            size_t token = (size_t)tile * MT + 8 * blk + i;
            *(float4*)(out + token * E_DIM + head * D_DIM + lane * 4) = o[i];
        }
    }
}

extern "C" void kernel_launch(void* const* d_in, const int* in_sizes, int n_in,
                              void* d_out, int out_size) {
    const float* x  = (const float*)d_in[0];
    const float* Wq = (const float*)d_in[1];
    const float* bq = (const float*)d_in[2];
    const float* Wk = (const float*)d_in[3];
    const float* bk = (const float*)d_in[4];
    const float* Wv = (const float*)d_in[5];
    const float* bv = (const float*)d_in[6];
    const float* P  = (const float*)d_in[7];
    float* out = (float*)d_out;

    const int tokens = in_sizes[0] / E_DIM;      // B*N
    const int tiles  = tokens / MT;              // 1024
    const size_t pre_smem = (size_t)PRE_SMEM_FLOATS * sizeof(float);   // 67,584 B
    const size_t smem     = (size_t)SMEM_FLOATS * sizeof(float);       // 104,960 B

    cudaFuncSetAttribute(pre_kernel,
                         cudaFuncAttributeMaxDynamicSharedMemorySize, (int)pre_smem);
    cudaFuncSetAttribute(fused_kernel,
                         cudaFuncAttributeMaxDynamicSharedMemorySize, (int)smem);

    pre_kernel<<<256 + tiles, 256, pre_smem>>>(x, Wq, bq, Wk, bk, Wv, bv, P);
    fused_kernel<<<tiles * 2, 256, smem>>>(out);
}